// round 16
// baseline (speedup 1.0000x reference)
#include <cuda_runtime.h>
#include <math_constants.h>

#define NPTS 4096
#define SEEDN 512
#define WARPS_PER_BLOCK 7
#define NTHREADS 224                          // 7 warps, 2 rows each
#define ROWS_PER_BLOCK 14
#define NBLOCKS 294                           // 294*14 = 4116 >= 4096
#define FULL 0xffffffffu

__device__ __forceinline__ bool pless(float da, int ia, float db, int ib) {
    return (da < db) || (da == db && ia < ib);
}
#define CAS(dx, ix, dy, iy)                                  \
    do { if (!pless(dx, ix, dy, iy)) {                       \
        float _t = dx; dx = dy; dy = _t;                     \
        int _u = ix; ix = iy; iy = _u; } } while (0)
#define CASV(a, b) do { float _lo = fminf(a, b), _hi = fmaxf(a, b); a = _lo; b = _hi; } while (0)

__device__ __forceinline__ void ins4(float dv, int j,
                                     float& d0, float& d1, float& d2, float& d3,
                                     int& i0, int& i1, int& i2, int& i3) {
    // warp-uniform; ascending j + strict '<' => exact top_k tie order
    d3 = dv; i3 = j;
    if (d3 < d2) { float t=d3; d3=d2; d2=t; int u=i3; i3=i2; i2=u; }
    if (d2 < d1) { float t=d2; d2=d1; d1=t; int u=i2; i2=i1; i1=u; }
    if (d1 < d0) { float t=d1; d1=d0; d0=t; int u=i1; i1=i0; i0=u; }
}

// value-only sorted-insert (e0<=e1<=e2<=e3)
#define VINS(v, e0, e1, e2, e3)                              \
    do { if ((v) < e3) { e3 = (v); CASV(e2, e3); CASV(e1, e2); CASV(e0, e1); } } while (0)

__global__ void __launch_bounds__(NTHREADS)
nn_tag_pool_kernel(const float2* __restrict__ obs1,
                   const float2* __restrict__ obs2,
                   const float*  __restrict__ W,
                   const float*  __restrict__ bias,
                   float* __restrict__ out)
{
    __shared__ __align__(16) float sx[NPTS];
    __shared__ __align__(16) float sy[NPTS];
    __shared__ __align__(16) float sn[NPTS];   // |p|^2

    const int tid = threadIdx.x;
    {   // stage: deinterleave + norms
        const float4* g4 = (const float4*)obs2;
        float2* sx2 = (float2*)sx;
        float2* sy2 = (float2*)sy;
        float2* sn2 = (float2*)sn;
        for (int m = tid; m < NPTS / 2; m += NTHREADS) {
            float4 v = g4[m];
            sx2[m] = make_float2(v.x, v.z);
            sy2[m] = make_float2(v.y, v.w);
            sn2[m] = make_float2(fmaf(v.x, v.x, v.y * v.y),
                                 fmaf(v.z, v.z, v.w * v.w));
        }
    }
    __syncthreads();

    const int warp = tid >> 5;
    const int lane = tid & 31;
    const int iA = blockIdx.x * ROWS_PER_BLOCK + warp * 2;  // even row
    const int iB = iA + 1;                                  // odd row
    if (iA >= NPTS) return;                   // whole-warp tail only (NPTS even)

    const float qxA = sx[iA], qyA = sy[iA];
    const float qxB = sx[iB], qyB = sy[iB];
    const float axA = -2.0f * qxA, ayA = -2.0f * qyA;
    const float axB = -2.0f * qxB, ayB = -2.0f * qyB;

    const float4* sx4 = (const float4*)sx;
    const float4* sy4 = (const float4*)sy;
    const float4* sn4 = (const float4*)sn;

    // selection value d'' = n - 2 q.p  (order == true dist; R14-validated)
    #define DA(X, Y, N) fmaf((X), axA, fmaf((Y), ayA, (N)))
    #define DB(X, Y, N) fmaf((X), axB, fmaf((Y), ayB, (N)))

    // ---------- seed: value-only exact 4th of [0,512) per row ----------
    float tauA, tauB;
    {
        float a0 = CUDART_INF_F, a1 = CUDART_INF_F, a2 = CUDART_INF_F, a3 = CUDART_INF_F;
        float b0 = CUDART_INF_F, b1 = CUDART_INF_F, b2 = CUDART_INF_F, b3 = CUDART_INF_F;
        #pragma unroll
        for (int g = 0; g < 4; ++g) {
            float4 X = sx4[g * 32 + lane];
            float4 Y = sy4[g * 32 + lane];
            float4 N = sn4[g * 32 + lane];
            const int jb = (g * 32 + lane) * 4;
            #pragma unroll
            for (int h = 0; h < 4; ++h) {
                float x = (h==0)?X.x:(h==1)?X.y:(h==2)?X.z:X.w;
                float y = (h==0)?Y.x:(h==1)?Y.y:(h==2)?Y.z:Y.w;
                float n = (h==0)?N.x:(h==1)?N.y:(h==2)?N.z:N.w;
                float vA = (jb + h == iA) ? CUDART_INF_F : DA(x, y, n);
                float vB = (jb + h == iB) ? CUDART_INF_F : DB(x, y, n);
                VINS(vA, a0, a1, a2, a3);
                VINS(vB, b0, b1, b2, b3);
            }
        }
        // values-only butterfly -> warp-uniform exact sorted-4; take 4th
        #pragma unroll
        for (int off = 16; off >= 1; off >>= 1) {
            float f0 = __shfl_xor_sync(FULL, a0, off);
            float f1 = __shfl_xor_sync(FULL, a1, off);
            float f2 = __shfl_xor_sync(FULL, a2, off);
            float f3 = __shfl_xor_sync(FULL, a3, off);
            float m0 = fminf(a0, f3), m1 = fminf(a1, f2);
            float m2 = fminf(a2, f1), m3 = fminf(a3, f0);
            CASV(m0, m2); CASV(m1, m3); CASV(m0, m1); CASV(m2, m3);
            a0 = m0; a1 = m1; a2 = m2; a3 = m3;

            float g0 = __shfl_xor_sync(FULL, b0, off);
            float g1 = __shfl_xor_sync(FULL, b1, off);
            float g2 = __shfl_xor_sync(FULL, b2, off);
            float g3 = __shfl_xor_sync(FULL, b3, off);
            float n0 = fminf(b0, g3), n1 = fminf(b1, g2);
            float n2 = fminf(b2, g1), n3 = fminf(b3, g0);
            CASV(n0, n2); CASV(n1, n3); CASV(n0, n1); CASV(n2, n3);
            b0 = n0; b1 = n1; b2 = n2; b3 = n3;
        }
        tauA = a3; tauB = b3;
    }

    // ---------- full scan [0,4096): warp-uniform lists, shared LDS ----------
    float dA0 = CUDART_INF_F, dA1 = CUDART_INF_F, dA2 = CUDART_INF_F, dA3 = CUDART_INF_F;
    int   iA0 = 0, iA1 = 0, iA2 = 0, iA3 = 0;
    float dB0 = CUDART_INF_F, dB1 = CUDART_INF_F, dB2 = CUDART_INF_F, dB3 = CUDART_INF_F;
    int   iB0 = 0, iB1 = 0, iB2 = 0, iB3 = 0;

    for (int s = 0; s < NPTS / 256; ++s) {    // 16 superiters, 8 pts/lane
        const int b4 = s * 64 + lane;
        float4 X0 = sx4[b4],      Y0 = sy4[b4],      N0 = sn4[b4];
        float4 X1 = sx4[b4 + 32], Y1 = sy4[b4 + 32], N1 = sn4[b4 + 32];

        float vA0 = DA(X0.x, Y0.x, N0.x), vA1 = DA(X0.y, Y0.y, N0.y);
        float vA2 = DA(X0.z, Y0.z, N0.z), vA3 = DA(X0.w, Y0.w, N0.w);
        float vA4 = DA(X1.x, Y1.x, N1.x), vA5 = DA(X1.y, Y1.y, N1.y);
        float vA6 = DA(X1.z, Y1.z, N1.z), vA7 = DA(X1.w, Y1.w, N1.w);
        float vB0 = DB(X0.x, Y0.x, N0.x), vB1 = DB(X0.y, Y0.y, N0.y);
        float vB2 = DB(X0.z, Y0.z, N0.z), vB3 = DB(X0.w, Y0.w, N0.w);
        float vB4 = DB(X1.x, Y1.x, N1.x), vB5 = DB(X1.y, Y1.y, N1.y);
        float vB6 = DB(X1.z, Y1.z, N1.z), vB7 = DB(X1.w, Y1.w, N1.w);

        float mgA0 = fminf(fminf(vA0, vA1), fminf(vA2, vA3));
        float mgA1 = fminf(fminf(vA4, vA5), fminf(vA6, vA7));
        float mgB0 = fminf(fminf(vB0, vB1), fminf(vB2, vB3));
        float mgB1 = fminf(fminf(vB4, vB5), fminf(vB6, vB7));

        float tA = fminf(tauA, dA3);
        float tB = fminf(tauB, dB3);

        // ONE ballot + uniform branch per 256 points x 2 rows
        bool hit = (fminf(mgA0, mgA1) <= tA) | (fminf(mgB0, mgB1) <= tB);
        if (__ballot_sync(FULL, hit)) {
            // ---- row A, group 0 (points s*256 + 4*r) ----
            unsigned mk = __ballot_sync(FULL, mgA0 <= tA);
            while (mk) {
                int r = __ffs(mk) - 1; mk &= mk - 1;
                float x0 = __shfl_sync(FULL, vA0, r);
                float x1 = __shfl_sync(FULL, vA1, r);
                float x2 = __shfl_sync(FULL, vA2, r);
                float x3 = __shfl_sync(FULL, vA3, r);
                int jb = s * 256 + 4 * r;
                if (jb+0 != iA && x0 < dA3) ins4(x0, jb+0, dA0,dA1,dA2,dA3, iA0,iA1,iA2,iA3);
                if (jb+1 != iA && x1 < dA3) ins4(x1, jb+1, dA0,dA1,dA2,dA3, iA0,iA1,iA2,iA3);
                if (jb+2 != iA && x2 < dA3) ins4(x2, jb+2, dA0,dA1,dA2,dA3, iA0,iA1,iA2,iA3);
                if (jb+3 != iA && x3 < dA3) ins4(x3, jb+3, dA0,dA1,dA2,dA3, iA0,iA1,iA2,iA3);
                if (mk) { tA = fminf(tauA, dA3); mk &= __ballot_sync(FULL, mgA0 <= tA); }
            }
            // ---- row A, group 1 (points s*256 + 128 + 4*r) ----
            tA = fminf(tauA, dA3);
            mk = __ballot_sync(FULL, mgA1 <= tA);
            while (mk) {
                int r = __ffs(mk) - 1; mk &= mk - 1;
                float x0 = __shfl_sync(FULL, vA4, r);
                float x1 = __shfl_sync(FULL, vA5, r);
                float x2 = __shfl_sync(FULL, vA6, r);
                float x3 = __shfl_sync(FULL, vA7, r);
                int jb = s * 256 + 128 + 4 * r;
                if (jb+0 != iA && x0 < dA3) ins4(x0, jb+0, dA0,dA1,dA2,dA3, iA0,iA1,iA2,iA3);
                if (jb+1 != iA && x1 < dA3) ins4(x1, jb+1, dA0,dA1,dA2,dA3, iA0,iA1,iA2,iA3);
                if (jb+2 != iA && x2 < dA3) ins4(x2, jb+2, dA0,dA1,dA2,dA3, iA0,iA1,iA2,iA3);
                if (jb+3 != iA && x3 < dA3) ins4(x3, jb+3, dA0,dA1,dA2,dA3, iA0,iA1,iA2,iA3);
                if (mk) { tA = fminf(tauA, dA3); mk &= __ballot_sync(FULL, mgA1 <= tA); }
            }
            // ---- row B, group 0 ----
            mk = __ballot_sync(FULL, mgB0 <= tB);
            while (mk) {
                int r = __ffs(mk) - 1; mk &= mk - 1;
                float x0 = __shfl_sync(FULL, vB0, r);
                float x1 = __shfl_sync(FULL, vB1, r);
                float x2 = __shfl_sync(FULL, vB2, r);
                float x3 = __shfl_sync(FULL, vB3, r);
                int jb = s * 256 + 4 * r;
                if (jb+0 != iB && x0 < dB3) ins4(x0, jb+0, dB0,dB1,dB2,dB3, iB0,iB1,iB2,iB3);
                if (jb+1 != iB && x1 < dB3) ins4(x1, jb+1, dB0,dB1,dB2,dB3, iB0,iB1,iB2,iB3);
                if (jb+2 != iB && x2 < dB3) ins4(x2, jb+2, dB0,dB1,dB2,dB3, iB0,iB1,iB2,iB3);
                if (jb+3 != iB && x3 < dB3) ins4(x3, jb+3, dB0,dB1,dB2,dB3, iB0,iB1,iB2,iB3);
                if (mk) { tB = fminf(tauB, dB3); mk &= __ballot_sync(FULL, mgB0 <= tB); }
            }
            // ---- row B, group 1 ----
            tB = fminf(tauB, dB3);
            mk = __ballot_sync(FULL, mgB1 <= tB);
            while (mk) {
                int r = __ffs(mk) - 1; mk &= mk - 1;
                float x0 = __shfl_sync(FULL, vB4, r);
                float x1 = __shfl_sync(FULL, vB5, r);
                float x2 = __shfl_sync(FULL, vB6, r);
                float x3 = __shfl_sync(FULL, vB7, r);
                int jb = s * 256 + 128 + 4 * r;
                if (jb+0 != iB && x0 < dB3) ins4(x0, jb+0, dB0,dB1,dB2,dB3, iB0,iB1,iB2,iB3);
                if (jb+1 != iB && x1 < dB3) ins4(x1, jb+1, dB0,dB1,dB2,dB3, iB0,iB1,iB2,iB3);
                if (jb+2 != iB && x2 < dB3) ins4(x2, jb+2, dB0,dB1,dB2,dB3, iB0,iB1,iB2,iB3);
                if (jb+3 != iB && x3 < dB3) ins4(x3, jb+3, dB0,dB1,dB2,dB3, iB0,iB1,iB2,iB3);
                if (mk) { tB = fminf(tauB, dB3); mk &= __ballot_sync(FULL, mgB1 <= tB); }
            }
        }
    }

    // ---------- epilogue (lists warp-uniform; no merge needed) ----------
    const int o = lane & 7;
    const float w0 = W[o * 6 + 0];
    const float w1 = W[o * 6 + 1];
    const float w3 = W[o * 6 + 3];
    const float w4 = W[o * 6 + 4];
    const float cb = W[o * 6 + 2] + W[o * 6 + 5] + bias[o];
    const int kk = lane >> 3;

    {   // row A
        const int j = (kk == 0) ? iA0 : (kk == 1) ? iA1 : (kk == 2) ? iA2 : iA3;
        const float pjx = sx[j], pjy = sy[j];
        const float2 a1j = obs1[j];
        const float2 a1i = obs1[iA];
        const float px = pjx - qxA, py = pjy - qyA;
        const float vx = (pjx - a1j.x) - (qxA - a1i.x);
        const float vy = (pjy - a1j.y) - (qyA - a1i.y);
        float r = fmaf(px, w0, fmaf(py, w1, fmaf(vx, w3, fmaf(vy, w4, cb))));
        out[iA * 32 + lane] = fmaxf(r, 0.0f);
    }
    {   // row B
        const int j = (kk == 0) ? iB0 : (kk == 1) ? iB1 : (kk == 2) ? iB2 : iB3;
        const float pjx = sx[j], pjy = sy[j];
        const float2 a1j = obs1[j];
        const float2 a1i = obs1[iB];
        const float px = pjx - qxB, py = pjy - qyB;
        const float vx = (pjx - a1j.x) - (qxB - a1i.x);
        const float vy = (pjy - a1j.y) - (qyB - a1i.y);
        float r = fmaf(px, w0, fmaf(py, w1, fmaf(vx, w3, fmaf(vy, w4, cb))));
        out[iB * 32 + lane] = fmaxf(r, 0.0f);
    }
}

extern "C" void kernel_launch(void* const* d_in, const int* in_sizes, int n_in,
                              void* d_out, int out_size) {
    const float2* obs1 = (const float2*)d_in[0];
    const float2* obs2 = (const float2*)d_in[1];
    const float*  Wp   = (const float*)d_in[2];
    const float*  bias = (const float*)d_in[3];
    float* out = (float*)d_out;

    nn_tag_pool_kernel<<<NBLOCKS, NTHREADS>>>(obs1, obs2, Wp, bias, out);
}

// round 17
// speedup vs baseline: 1.1349x; 1.1349x over previous
#include <cuda_runtime.h>
#include <math_constants.h>

#define NPTS 4096
#define SEEDN 512
#define WARPS_PER_BLOCK 28
#define NTHREADS (WARPS_PER_BLOCK * 32)      // 896
#define NBLOCKS 147                           // 1 block/SM
#define NSUPER ((NPTS - SEEDN) / 256)         // 14 superiters of 256 points
#define FULL 0xffffffffu

__device__ __forceinline__ bool pless(float da, int ia, float db, int ib) {
    return (da < db) || (da == db && ia < ib);
}
#define CAS(dx, ix, dy, iy)                                  \
    do { if (!pless(dx, ix, dy, iy)) {                       \
        float _t = dx; dx = dy; dy = _t;                     \
        int _u = ix; ix = iy; iy = _u; } } while (0)

__device__ __forceinline__ void ins4(float dv, int j,
                                     float& d0, float& d1, float& d2, float& d3,
                                     int& i0, int& i1, int& i2, int& i3) {
    // ascending j + strict '<' => exact top_k tie order
    d3 = dv; i3 = j;
    if (d3 < d2) { float t=d3; d3=d2; d2=t; int u=i3; i3=i2; i2=u; }
    if (d2 < d1) { float t=d2; d2=d1; d1=t; int u=i2; i2=i1; i1=u; }
    if (d1 < d0) { float t=d1; d1=d0; d0=t; int u=i1; i1=i0; i0=u; }
}

__global__ void __launch_bounds__(NTHREADS)
nn_tag_pool_kernel(const float2* __restrict__ obs1,
                   const float2* __restrict__ obs2,
                   const float*  __restrict__ W,
                   const float*  __restrict__ bias,
                   float* __restrict__ out)
{
    __shared__ __align__(16) float sx[NPTS];
    __shared__ __align__(16) float sy[NPTS];

    const int tid = threadIdx.x;
    {   // stage + deinterleave: obs2 AoS float2 -> SoA sx/sy
        const float4* g4 = (const float4*)obs2;
        for (int m = tid; m < NPTS / 2; m += NTHREADS) {
            float4 v = g4[m];                 // {x0,y0,x1,y1}
            sx[2*m]   = v.x;  sy[2*m]   = v.y;
            sx[2*m+1] = v.z;  sy[2*m+1] = v.w;
        }
    }
    __syncthreads();

    const int warp = tid >> 5;
    const int lane = tid & 31;
    const int i = blockIdx.x * WARPS_PER_BLOCK + warp;   // query row
    if (i >= NPTS) return;                    // whole tail warps only

    const float qx = sx[i], qy = sy[i];

    const float4* sx4 = (const float4*)sx;
    const float4* sy4 = (const float4*)sy;

    // ---------- seed: per-lane private top-4 over 16 pts of [0,512) ----------
    float d0 = CUDART_INF_F, d1 = CUDART_INF_F, d2 = CUDART_INF_F, d3 = CUDART_INF_F;
    int   i0 = 0x7fffffff,  i1 = 0x7fffffff,  i2 = 0x7fffffff,  i3 = 0x7fffffff;

    #pragma unroll
    for (int g = 0; g < 4; ++g) {             // strided: conflict-free LDS.128
        float4 X = sx4[g * 32 + lane];
        float4 Y = sy4[g * 32 + lane];
        const int jb = (g * 32 + lane) * 4;
        #pragma unroll
        for (int h = 0; h < 4; ++h) {
            float px = (h == 0) ? X.x : (h == 1) ? X.y : (h == 2) ? X.z : X.w;
            float py = (h == 0) ? Y.x : (h == 1) ? Y.y : (h == 2) ? Y.z : Y.w;
            float ddx = px - qx, ddy = py - qy;
            float dv = fmaf(ddx, ddx, fmaf(ddy, ddy, 1.0f));
            int j = jb + h;                   // ascending j within lane
            if (j != i && dv < d3)
                ins4(dv, j, d0, d1, d2, d3, i0, i1, i2, i3);
        }
    }

    // indexed butterfly merge: 32 private sorted-4 -> warp-uniform top-4 of [0,512)
    #pragma unroll
    for (int off = 16; off >= 1; off >>= 1) {
        float f0 = __shfl_xor_sync(FULL, d0, off);
        float f1 = __shfl_xor_sync(FULL, d1, off);
        float f2 = __shfl_xor_sync(FULL, d2, off);
        float f3 = __shfl_xor_sync(FULL, d3, off);
        int   g0 = __shfl_xor_sync(FULL, i0, off);
        int   g1 = __shfl_xor_sync(FULL, i1, off);
        int   g2 = __shfl_xor_sync(FULL, i2, off);
        int   g3 = __shfl_xor_sync(FULL, i3, off);

        float m0, m1, m2, m3; int n0, n1, n2, n3;
        if (pless(d0, i0, f3, g3)) { m0 = d0; n0 = i0; } else { m0 = f3; n0 = g3; }
        if (pless(d1, i1, f2, g2)) { m1 = d1; n1 = i1; } else { m1 = f2; n1 = g2; }
        if (pless(d2, i2, f1, g1)) { m2 = d2; n2 = i2; } else { m2 = f1; n2 = g1; }
        if (pless(d3, i3, f0, g0)) { m3 = d3; n3 = i3; } else { m3 = f0; n3 = g0; }

        CAS(m0, n0, m2, n2); CAS(m1, n1, m3, n3);
        CAS(m0, n0, m1, n1); CAS(m2, n2, m3, n3);

        d0 = m0; d1 = m1; d2 = m2; d3 = m3;
        i0 = n0; i1 = n1; i2 = n2; i3 = n3;
    }
    // list now warp-uniform and EXACT over [0,512); d3 = tight threshold

    // ---------- main scan: [512,4096), software-pipelined superiters --------
    // prefetch superiter 0's tile
    float4 XA = sx4[(SEEDN / 4) + lane];
    float4 YA = sy4[(SEEDN / 4) + lane];
    float4 XB = sx4[(SEEDN / 4) + 32 + lane];
    float4 YB = sy4[(SEEDN / 4) + 32 + lane];

    for (int s = 0; s < NSUPER; ++s) {
        // compute distances from the prefetched tile (current superiter)
        float dxa = XA.x - qx, dya = YA.x - qy;
        float dxb = XA.y - qx, dyb = YA.y - qy;
        float dxc = XA.z - qx, dyc = YA.z - qy;
        float dxd = XA.w - qx, dyd = YA.w - qy;
        float va0 = fmaf(dxa, dxa, fmaf(dya, dya, 1.0f));
        float va1 = fmaf(dxb, dxb, fmaf(dyb, dyb, 1.0f));
        float va2 = fmaf(dxc, dxc, fmaf(dyc, dyc, 1.0f));
        float va3 = fmaf(dxd, dxd, fmaf(dyd, dyd, 1.0f));
        float exa = XB.x - qx, eya = YB.x - qy;
        float exb = XB.y - qx, eyb = YB.y - qy;
        float exc = XB.z - qx, eyc = YB.z - qy;
        float exd = XB.w - qx, eyd = YB.w - qy;
        float vb0 = fmaf(exa, exa, fmaf(eya, eya, 1.0f));
        float vb1 = fmaf(exb, exb, fmaf(eyb, eyb, 1.0f));
        float vb2 = fmaf(exc, exc, fmaf(eyc, eyc, 1.0f));
        float vb3 = fmaf(exd, exd, fmaf(eyd, eyd, 1.0f));

        // prefetch NEXT superiter's tile BEFORE ballot/branch (overlap latency)
        {
            const int ns = (s + 1 < NSUPER) ? s + 1 : s;     // clamp, no predication
            const int nb4 = (SEEDN / 4) + ns * 64 + lane;
            XA = sx4[nb4];       YA = sy4[nb4];
            XB = sx4[nb4 + 32];  YB = sy4[nb4 + 32];
        }

        float mga = fminf(fminf(va0, va1), fminf(va2, va3));
        float mgb = fminf(fminf(vb0, vb1), fminf(vb2, vb3));

        // ONE ballot + uniform branch per 256 points
        if (__ballot_sync(FULL, fminf(mga, mgb) < d3)) {
            // group A: points SEEDN + s*256 + [0,128)
            unsigned mk = __ballot_sync(FULL, mga < d3);
            while (mk) {                       // warp-uniform, rare
                int r = __ffs(mk) - 1;
                mk &= mk - 1;
                float x0 = __shfl_sync(FULL, va0, r);
                float x1 = __shfl_sync(FULL, va1, r);
                float x2 = __shfl_sync(FULL, va2, r);
                float x3 = __shfl_sync(FULL, va3, r);
                int jb = SEEDN + s * 256 + 4 * r;
                if (jb + 0 != i && x0 < d3) ins4(x0, jb + 0, d0,d1,d2,d3, i0,i1,i2,i3);
                if (jb + 1 != i && x1 < d3) ins4(x1, jb + 1, d0,d1,d2,d3, i0,i1,i2,i3);
                if (jb + 2 != i && x2 < d3) ins4(x2, jb + 2, d0,d1,d2,d3, i0,i1,i2,i3);
                if (jb + 3 != i && x3 < d3) ins4(x3, jb + 3, d0,d1,d2,d3, i0,i1,i2,i3);
                if (mk) mk &= __ballot_sync(FULL, mga < d3);
            }
            // group B: points SEEDN + s*256 + [128,256)
            mk = __ballot_sync(FULL, mgb < d3);
            while (mk) {
                int r = __ffs(mk) - 1;
                mk &= mk - 1;
                float x0 = __shfl_sync(FULL, vb0, r);
                float x1 = __shfl_sync(FULL, vb1, r);
                float x2 = __shfl_sync(FULL, vb2, r);
                float x3 = __shfl_sync(FULL, vb3, r);
                int jb = SEEDN + s * 256 + 128 + 4 * r;
                if (jb + 0 != i && x0 < d3) ins4(x0, jb + 0, d0,d1,d2,d3, i0,i1,i2,i3);
                if (jb + 1 != i && x1 < d3) ins4(x1, jb + 1, d0,d1,d2,d3, i0,i1,i2,i3);
                if (jb + 2 != i && x2 < d3) ins4(x2, jb + 2, d0,d1,d2,d3, i0,i1,i2,i3);
                if (jb + 3 != i && x3 < d3) ins4(x3, jb + 3, d0,d1,d2,d3, i0,i1,i2,i3);
                if (mk) mk &= __ballot_sync(FULL, mgb < d3);
            }
        }
    }

    // ---------- epilogue: list warp-uniform; lane kk*8+o -> channel o --------
    const int o = lane & 7;
    const float w0 = W[o * 6 + 0];
    const float w1 = W[o * 6 + 1];
    const float w3 = W[o * 6 + 3];
    const float w4 = W[o * 6 + 4];
    const float cb = W[o * 6 + 2] + W[o * 6 + 5] + bias[o];

    const int kk = lane >> 3;
    const int j = (kk == 0) ? i0 : (kk == 1) ? i1 : (kk == 2) ? i2 : i3;

    const float pjx = sx[j], pjy = sy[j];
    const float2 a1j = obs1[j];
    const float2 a1i = obs1[i];

    const float px = pjx - qx;
    const float py = pjy - qy;
    const float vx = (pjx - a1j.x) - (qx - a1i.x);   // vel[j] - vel[i]
    const float vy = (pjy - a1j.y) - (qy - a1i.y);

    float r = fmaf(px, w0, fmaf(py, w1, fmaf(vx, w3, fmaf(vy, w4, cb))));
    out[i * 32 + lane] = fmaxf(r, 0.0f);
}

extern "C" void kernel_launch(void* const* d_in, const int* in_sizes, int n_in,
                              void* d_out, int out_size) {
    const float2* obs1 = (const float2*)d_in[0];
    const float2* obs2 = (const float2*)d_in[1];
    const float*  Wp   = (const float*)d_in[2];
    const float*  bias = (const float*)d_in[3];
    float* out = (float*)d_out;

    nn_tag_pool_kernel<<<NBLOCKS, NTHREADS>>>(obs1, obs2, Wp, bias, out);
}